// round 13
// baseline (speedup 1.0000x reference)
#include <cuda_runtime.h>
#include <cuda_fp16.h>
#include <cstdint>

// Problem constants
#define BB   32
#define TT   64
#define SS   64
#define HH   256
#define VV   32000

// ---------------------------------------------------------------------------
// PTX helpers
// ---------------------------------------------------------------------------
__device__ __forceinline__ uint32_t smem_u32(const void* p) {
    uint32_t a;
    asm("{ .reg .u64 t; cvta.to.shared.u64 t, %1; cvt.u32.u64 %0, t; }" : "=r"(a) : "l"(p));
    return a;
}
__device__ __forceinline__ void cp_async16(uint32_t dst, const void* src) {
    asm volatile("cp.async.cg.shared.global [%0], [%1], 16;" :: "r"(dst), "l"(src));
}
#define CP_COMMIT() asm volatile("cp.async.commit_group;" ::: "memory")
#define CP_WAIT(n)  asm volatile("cp.async.wait_group %0;" :: "n"(n) : "memory")

__device__ __forceinline__ void ldsm_x4(uint32_t addr, uint32_t& r0, uint32_t& r1,
                                        uint32_t& r2, uint32_t& r3) {
    asm volatile("ldmatrix.sync.aligned.m8n8.x4.shared.b16 {%0,%1,%2,%3}, [%4];"
                 : "=r"(r0), "=r"(r1), "=r"(r2), "=r"(r3) : "r"(addr));
}
__device__ __forceinline__ void mma16816(float* c, const uint32_t* a,
                                         uint32_t b0, uint32_t b1) {
    asm volatile("mma.sync.aligned.m16n8k16.row.col.f32.f16.f16.f32 "
                 "{%0,%1,%2,%3}, {%4,%5,%6,%7}, {%8,%9}, {%0,%1,%2,%3};"
                 : "+f"(c[0]), "+f"(c[1]), "+f"(c[2]), "+f"(c[3])
                 : "r"(a[0]), "r"(a[1]), "r"(a[2]), "r"(a[3]), "r"(b0), "r"(b1));
}
__device__ __forceinline__ uint32_t ctarank() {
    uint32_t r; asm("mov.u32 %0, %%cluster_ctarank;" : "=r"(r)); return r;
}
__device__ __forceinline__ uint32_t mapa_u32(uint32_t laddr, uint32_t rank) {
    uint32_t r;
    asm("mapa.shared::cluster.u32 %0, %1, %2;" : "=r"(r) : "r"(laddr), "r"(rank));
    return r;
}
__device__ __forceinline__ void st_cluster_f32(uint32_t addr, float v) {
    asm volatile("st.shared::cluster.f32 [%0], %1;" :: "r"(addr), "f"(v) : "memory");
}
#define CLUSTER_SYNC() do { \
    asm volatile("barrier.cluster.arrive.aligned;" ::: "memory"); \
    asm volatile("barrier.cluster.wait.aligned;" ::: "memory"); \
} while (0)
#define CLUSTER_ARRIVE() asm volatile("barrier.cluster.arrive.aligned;" ::: "memory")
#define CLUSTER_WAIT()   asm volatile("barrier.cluster.wait.aligned;" ::: "memory")

// ---------------------------------------------------------------------------
// Device scratch
// ---------------------------------------------------------------------------
__device__ __align__(16) float g_Wcat[256 * 1024];     // [k][qproj|Whz|Whr|Whh]
__device__ __align__(16) float g_bcat[1024];
__device__ __align__(16) float g_Wann[256 * 1024];
__device__ __align__(16) float g_Wx[256 * 768];
__device__ __align__(16) float g_annprojB[2048 * 256]; // [(b*S+s)][256]  (+b1)
__device__ __align__(16) float g_annWi[2048 * 768];    // [(b*S+s)][768]
__device__ __align__(16) float g_xproj[2048 * 768];    // [(t*B+b)][768]  (+bi*)
__device__ __align__(16) __half g_Ah[2048 * 512];      // [A_hi(256)|A_lo(256)]
__device__ __align__(16) __half g_Bh[32000L * 256];    // B_hi only, K-major

// ---------------------------------------------------------------------------
// K0: build fused weight matrices
// ---------------------------------------------------------------------------
__global__ void prep_kernel(const float* __restrict__ W1,
                            const float* __restrict__ Wiz, const float* __restrict__ Wir,
                            const float* __restrict__ Wih,
                            const float* __restrict__ Whz, const float* __restrict__ bhz,
                            const float* __restrict__ Whr, const float* __restrict__ bhr,
                            const float* __restrict__ Whh, const float* __restrict__ bhh) {
    int idx = blockIdx.x * blockDim.x + threadIdx.x;
    int stride = gridDim.x * blockDim.x;
    for (int i = idx; i < 256 * 1024; i += stride) {
        int k = i >> 10, j = i & 1023;
        float wc, wa;
        if (j < 256)      { wc = W1[k * 256 + j];          wa = W1[(256 + k) * 256 + j]; }
        else if (j < 512) { wc = Whz[k * 256 + j - 256];   wa = Wiz[k * 256 + j - 256]; }
        else if (j < 768) { wc = Whr[k * 256 + j - 512];   wa = Wir[k * 256 + j - 512]; }
        else              { wc = Whh[k * 256 + j - 768];   wa = Wih[k * 256 + j - 768]; }
        g_Wcat[i] = wc; g_Wann[i] = wa;
    }
    for (int i = idx; i < 256 * 768; i += stride) {
        int k = i / 768, j = i % 768;
        float w;
        if (j < 256)      w = Wiz[(256 + k) * 256 + j];
        else if (j < 512) w = Wir[(256 + k) * 256 + j - 256];
        else              w = Wih[(256 + k) * 256 + j - 512];
        g_Wx[i] = w;
    }
    for (int i = idx; i < 1024; i += stride) {
        float bv = 0.f;
        if (i >= 256 && i < 512)      bv = bhz[i - 256];
        else if (i >= 512 && i < 768) bv = bhr[i - 512];
        else if (i >= 768)            bv = bhh[i - 768];
        g_bcat[i] = bv;
    }
}

// ---------------------------------------------------------------------------
// K1 combo: sgemm mode1 (512 CTAs) + sgemm mode2 (384) + Wout->fp16 (4000)
// ---------------------------------------------------------------------------
__global__ void __launch_bounds__(128)
combo_kernel(const float* __restrict__ ann, const float* __restrict__ emb,
             const int* __restrict__ inputs, const float* __restrict__ Wout,
             const float* __restrict__ b1, const float* __restrict__ biz,
             const float* __restrict__ bir, const float* __restrict__ bih) {
    __shared__ __align__(16) float sm[2][64 * 20 + 16 * 68];
    __shared__ __align__(16) float sw[32 * 68];
    __shared__ int tok[64];

    const int bid = blockIdx.x, tid = threadIdx.x;

    if (bid >= 896) {
        int b3 = bid - 896;
        int k0 = (b3 & 7) * 32, n0 = (b3 >> 3) * 64;
        for (int i = tid; i < 32 * 64; i += 128) {
            int k = i >> 6, n = i & 63;
            sw[k * 68 + n] = Wout[(size_t)(k0 + k) * VV + n0 + n];
        }
        __syncthreads();
        const int n = tid >> 1, kh = (tid & 1) * 16;
        __align__(16) __half vals[16];
#pragma unroll
        for (int j = 0; j < 16; j++) vals[j] = __float2half(sw[(kh + j) * 68 + n]);
        __half* dst = g_Bh + (size_t)(n0 + n) * 256 + k0 + kh;
        *(uint4*)dst       = ((const uint4*)vals)[0];
        *(uint4*)(dst + 8) = ((const uint4*)vals)[1];
        return;
    }

    const bool m1 = bid < 512;
    int row0, col0, N;
    const float* Bm;
    if (m1) { row0 = (bid >> 4) * 64; col0 = (bid & 15) * 64; N = 1024; Bm = g_Wann; }
    else    { int b2 = bid - 512; row0 = (b2 / 12) * 64; col0 = (b2 % 12) * 64; N = 768; Bm = g_Wx; }

    if (!m1 && tid < 64) {
        int r = row0 + tid;
        tok[tid] = inputs[(r & 31) * TT + (r >> 5)];
    }
    if (!m1) __syncthreads();

    const int rA = tid >> 2, kqA = (tid & 3) * 4;
    const int kB = tid >> 4, nB = (tid & 15) * 4;
    const float* ArowA = m1 ? (ann + (size_t)(row0 + rA) * 256)
                            : (emb + (size_t)tok[rA] * 256);
    const float* ArowB = m1 ? (ann + (size_t)(row0 + rA + 32) * 256)
                            : (emb + (size_t)tok[rA + 32] * 256);
    const float* Bcol = Bm + col0;

    {
        float4 a0 = *(const float4*)(ArowA + kqA);
        float4 a1 = *(const float4*)(ArowB + kqA);
        float4 b0 = *(const float4*)(Bcol + (size_t)kB * N + nB);
        float4 b1v = *(const float4*)(Bcol + (size_t)(kB + 8) * N + nB);
        *(float4*)&sm[0][rA * 20 + kqA]        = a0;
        *(float4*)&sm[0][(rA + 32) * 20 + kqA] = a1;
        *(float4*)&sm[0][1280 + kB * 68 + nB]        = b0;
        *(float4*)&sm[0][1280 + (kB + 8) * 68 + nB]  = b1v;
    }
    __syncthreads();

    float acc[4][8];
#pragma unroll
    for (int i = 0; i < 4; i++)
#pragma unroll
        for (int j = 0; j < 8; j++) acc[i][j] = 0.f;

    const int ty4 = (tid >> 3) * 4, tx8 = (tid & 7) * 8;
    int buf = 0;

#pragma unroll 1
    for (int kt = 0; kt < 16; kt++) {
        float4 nA0, nA1, nB0, nB1;
        if (kt < 15) {
            int k0 = (kt + 1) * 16;
            nA0 = *(const float4*)(ArowA + k0 + kqA);
            nA1 = *(const float4*)(ArowB + k0 + kqA);
            nB0 = *(const float4*)(Bcol + (size_t)(k0 + kB) * N + nB);
            nB1 = *(const float4*)(Bcol + (size_t)(k0 + kB + 8) * N + nB);
        }
        const float* As_ = &sm[buf][0];
        const float* Bs_ = &sm[buf][1280];
#pragma unroll
        for (int kk = 0; kk < 16; kk++) {
            float a[4], b[8];
#pragma unroll
            for (int i = 0; i < 4; i++) a[i] = As_[(ty4 + i) * 20 + kk];
            *(float4*)&b[0] = *(const float4*)&Bs_[kk * 68 + tx8];
            *(float4*)&b[4] = *(const float4*)&Bs_[kk * 68 + tx8 + 4];
#pragma unroll
            for (int i = 0; i < 4; i++)
#pragma unroll
                for (int j = 0; j < 8; j++) acc[i][j] += a[i] * b[j];
        }
        if (kt < 15) {
            buf ^= 1;
            __syncthreads();
            *(float4*)&sm[buf][rA * 20 + kqA]        = nA0;
            *(float4*)&sm[buf][(rA + 32) * 20 + kqA] = nA1;
            *(float4*)&sm[buf][1280 + kB * 68 + nB]        = nB0;
            *(float4*)&sm[buf][1280 + (kB + 8) * 68 + nB]  = nB1;
            __syncthreads();
        }
    }

#pragma unroll
    for (int i = 0; i < 4; i++) {
        int r = row0 + ty4 + i;
#pragma unroll
        for (int j = 0; j < 8; j++) {
            int cidx = col0 + tx8 + j;
            float v = acc[i][j];
            if (m1) {
                if (cidx < 256) g_annprojB[(size_t)r * 256 + cidx] = v + b1[cidx];
                else            g_annWi[(size_t)r * 768 + (cidx - 256)] = v;
            } else {
                float bv = (cidx < 256) ? biz[cidx]
                         : (cidx < 512) ? bir[cidx - 256] : bih[cidx - 512];
                g_xproj[(size_t)r * 768 + cidx] = v + bv;
            }
        }
    }
}

// ---------------------------------------------------------------------------
// K3: clustered recurrence (identical to R10/R12 - passing)
// ---------------------------------------------------------------------------
#define O_WS   0        // [k 0..255][j 0..127]  weights, j contiguous
#define O_QT   32768    // [bb][c 0..31][s 0..63] annproj transposed
#define O_TILE 36864    // [bb][s 0..63][c 0..95] annWi (z|r|h) pitch 96
#define O_HS   49152    // 2 x 256 hidden state
#define O_HC   49664    // 2 x 128 hcat slice
#define O_PA   49920    // 4 kq x (2 bb x 128 j) phase-A partials
#define O_UPA  50944    // 8 x 128 logit partials (all-gathered)
#define O_AL   51968    // 2 x 64 alpha
#define O_ZR   52096    // 2 x 64 (z | r)
#define O_PHB  52224    // 2 x 32 hbar pre
#define O_BS   52288    // 128 bias
#define O_W2   52416    // 32
#define REC_NF 52448
#define REC_DSMEM (REC_NF * 4)

__global__ void __launch_bounds__(512, 1) __cluster_dims__(8, 1, 1)
recurrence_kernel(const float* __restrict__ hidden_init,
                  const float* __restrict__ W2,
                  float* __restrict__ att_out) {
    extern __shared__ __align__(16) float dsm[];

    const int tid = threadIdx.x;
    const uint32_t q = ctarank();
    const int b0 = (blockIdx.x >> 3) * 2;
    const uint32_t sbase = smem_u32(dsm);

    // ---- init ----
    for (int i = tid; i < 256 * 128; i += 512) {
        int k = i >> 7, j = i & 127;
        int gcol = (j >> 5) * 256 + (int)q * 32 + (j & 31);
        dsm[O_WS + k * 128 + j] = g_Wcat[k * 1024 + gcol];
    }
    for (int i = tid; i < 2 * 32 * 64; i += 512) {
        int bb = i >> 11, c = (i >> 6) & 31, s = i & 63;
        dsm[O_QT + i] = g_annprojB[(size_t)((b0 + bb) * 64 + s) * 256 + q * 32 + c];
    }
    for (int i = tid; i < 2 * 64 * 96; i += 512) {
        int bb = i / 6144, rem = i % 6144;
        int s = rem / 96, c = rem % 96;
        dsm[O_TILE + i] = g_annWi[(size_t)((b0 + bb) * 64 + s) * 768
                                  + (c >> 5) * 256 + q * 32 + (c & 31)];
    }
    if (tid < 128) {
        int gcol = (tid >> 5) * 256 + (int)q * 32 + (tid & 31);
        dsm[O_BS + tid] = g_bcat[gcol];
    }
    if (tid >= 128 && tid < 160) dsm[O_W2 + tid - 128] = W2[q * 32 + (tid - 128)];
    for (int i = tid; i < 512; i += 512)
        dsm[O_HS + i] = hidden_init[(b0 + (i >> 8)) * 256 + (i & 255)];
    __syncthreads();
    CLUSTER_SYNC();

    // register xproj prefetch state (gate threads tid<192)
    const int gbb = (tid >= 96 && tid < 192) ? 1 : 0;
    const int gcc = (tid < 192) ? (tid - gbb * 96) : 0;
    const size_t xoff = (size_t)((gcc >> 5) * 256 + (int)q * 32 + (gcc & 31));
    float xp = 0.f;
    if (tid < 192)
        xp = g_xproj[(size_t)(b0 + gbb) * 768 + xoff];

#pragma unroll 1
    for (int t = 0; t < TT; t++) {
        // ---- (1) phase A: hcat, k split 4 ways over 512 threads ----
        {
            const int j = tid & 127;
            const int kq = tid >> 7;               // 0..3
            const float* wp = &dsm[O_WS + kq * 64 * 128 + j];
            const float* h0 = &dsm[O_HS + kq * 64];
            const float* h1 = &dsm[O_HS + 256 + kq * 64];
            float a0 = 0.f, a1 = 0.f;
#pragma unroll
            for (int k = 0; k < 64; k += 4) {
                float4 hv0 = *(const float4*)(h0 + k);
                float4 hv1 = *(const float4*)(h1 + k);
                float w0 = wp[k * 128], w1 = wp[(k + 1) * 128];
                float w2v = wp[(k + 2) * 128], w3 = wp[(k + 3) * 128];
                a0 += hv0.x * w0 + hv0.y * w1 + hv0.z * w2v + hv0.w * w3;
                a1 += hv1.x * w0 + hv1.y * w1 + hv1.z * w2v + hv1.w * w3;
            }
            dsm[O_PA + kq * 256 + j]       = a0;
            dsm[O_PA + kq * 256 + 128 + j] = a1;
        }
        __syncthreads();                                       // s0
        if (tid < 256) {
            int bb = tid >> 7, jj = tid & 127;
            float v = dsm[O_BS + jj]
                    + dsm[O_PA + bb * 128 + jj]       + dsm[O_PA + 256 + bb * 128 + jj]
                    + dsm[O_PA + 512 + bb * 128 + jj] + dsm[O_PA + 768 + bb * 128 + jj];
            dsm[O_HC + bb * 128 + jj] = v;
        }
        __syncthreads();                                       // s1

        // ---- (2) logits: 128 threads, push to all 8 ranks ----
        if (tid < 128) {
            const int bb = tid >> 6, s = tid & 63;
            const float* qt = &dsm[O_QT + bb * 2048 + s];
            const float* hq = &dsm[O_HC + bb * 128];
            const float* w2 = &dsm[O_W2];
            float u0 = 0.f, u1 = 0.f;
#pragma unroll
            for (int c = 0; c < 32; c += 4) {
                float4 hv = *(const float4*)(hq + c);
                float4 wv = *(const float4*)(w2 + c);
                u0 += wv.x * fmaxf(hv.x + qt[c * 64], 0.f)
                    + wv.y * fmaxf(hv.y + qt[(c + 1) * 64], 0.f);
                u1 += wv.z * fmaxf(hv.z + qt[(c + 2) * 64], 0.f)
                    + wv.w * fmaxf(hv.w + qt[(c + 3) * 64], 0.f);
            }
            float u = u0 + u1;
            uint32_t la = sbase + (O_UPA + (int)q * 128 + tid) * 4;
#pragma unroll
            for (int rk = 0; rk < 8; rk++)
                st_cluster_f32(mapa_u32(la, rk), u);
        }
        CLUSTER_SYNC();                                        // CS1

        // ---- (3) softmax: warp-redundant ----
        if (tid < 64) {
            const int bb = tid >> 5, lane = tid & 31;
            float u0 = 0.f, u1 = 0.f;
#pragma unroll
            for (int r = 0; r < 8; r++) {
                u0 += dsm[O_UPA + r * 128 + bb * 64 + lane];
                u1 += dsm[O_UPA + r * 128 + bb * 64 + 32 + lane];
            }
            float m = fmaxf(u0, u1);
#pragma unroll
            for (int o = 16; o; o >>= 1) m = fmaxf(m, __shfl_xor_sync(0xffffffffu, m, o));
            float e0 = __expf(u0 - m), e1 = __expf(u1 - m);
            float sum = e0 + e1;
#pragma unroll
            for (int o = 16; o; o >>= 1) sum += __shfl_xor_sync(0xffffffffu, sum, o);
            float inv = 1.f / sum;
            float a0 = e0 * inv, a1 = e1 * inv;
            dsm[O_AL + bb * 64 + lane]      = a0;
            dsm[O_AL + bb * 64 + 32 + lane] = a1;
            if (q == 0) {
                att_out[((b0 + bb) * SS + lane) * TT + t]      = a0;
                att_out[((b0 + bb) * SS + 32 + lane) * TT + t] = a1;
            }
        }
        __syncthreads();                                       // s2

        // ---- (4) gate sums + activations ----
        if (tid < 192) {
            const float* tp = &dsm[O_TILE + gbb * 6144 + gcc];
            const float* ap = &dsm[O_AL + gbb * 64];
            float acc0 = 0.f, acc1 = 0.f;
#pragma unroll 8
            for (int s = 0; s < 64; s += 2) {
                acc0 += ap[s] * tp[s * 96];
                acc1 += ap[s + 1] * tp[(s + 1) * 96];
            }
            float pre = acc0 + acc1 + xp;
            if (gcc < 64) {
                float v = 1.f / (1.f + __expf(-(pre + dsm[O_HC + gbb * 128 + 32 + gcc])));
                dsm[O_ZR + gbb * 64 + gcc] = v;
            } else {
                dsm[O_PHB + gbb * 32 + gcc - 64] = pre;
            }
        }
        __syncthreads();                                       // s3

        // ---- (5) GRU combine + h broadcast ----
        if (tid < 64) {
            int bb = tid >> 5, jj = tid & 31;
            int dg = (int)q * 32 + jj;
            float z = dsm[O_ZR + bb * 64 + jj];
            float r = dsm[O_ZR + bb * 64 + 32 + jj];
            float g = tanhf(dsm[O_PHB + bb * 32 + jj] + r * dsm[O_HC + bb * 128 + 96 + jj]);
            float hold = dsm[O_HS + bb * 256 + dg];
            float hn = (1.f - z) * g + z * hold;
            uint32_t la = sbase + (O_HS + bb * 256 + dg) * 4;
#pragma unroll
            for (int rk = 0; rk < 8; rk++)
                st_cluster_f32(mapa_u32(la, rk), hn);
            __half hi = __float2half(hn);
            __half lo = __float2half(hn - __half2float(hi));
            size_t rb = (size_t)((b0 + bb) * 64 + t) * 512;
            g_Ah[rb + dg]       = hi;
            g_Ah[rb + 256 + dg] = lo;
        }
        CLUSTER_ARRIVE();                                      // CS2 arrive
        if (tid < 192 && t + 1 < TT)                           // prefetch next xproj
            xp = g_xproj[(size_t)((t + 1) * 32 + b0 + gbb) * 768 + xoff];
        CLUSTER_WAIT();                                        // CS2 wait
    }
}

// ---------------------------------------------------------------------------
// K4: HMMA fp16 GEMM — CTA 128x256, 8 warps of 64x64, 256 threads, 1 CTA/SM.
// Per-SM per-kt: smem ~704cyc < tensor 1024cyc -> tensor-bound.
// ---------------------------------------------------------------------------
#define GSTAGES 3

__global__ void __launch_bounds__(256, 1)
gemm_mma_kernel(const float* __restrict__ bout, float* __restrict__ out) {
    __shared__ __align__(128) __half sA[GSTAGES][128 * 32];
    __shared__ __align__(128) __half sB[GSTAGES][256 * 32];

    const int tid  = threadIdx.x;
    const int lane = tid & 31, wid = tid >> 5;
    const int wr = wid >> 2, wc = wid & 3;           // 2 x 4 grid of 64x64
    const int row0 = blockIdx.x * 128, col0 = blockIdx.y * 256;

    const __half* Ag = g_Ah + (size_t)row0 * 512;
    const __half* Bg = g_Bh + (size_t)col0 * 256;

    const uint32_t sAb = smem_u32(sA);
    const uint32_t sBb = smem_u32(sB);

    // loader: 512 A-chunks + 1024 B-chunks per stage, 6 per thread
    const int cL = tid & 3;
    const int rL = tid >> 2;                          // 0..63

#define LOAD_STAGE(s, kt) do {                                                        \
        uint32_t ab = sAb + (s) * 8192, bbx = sBb + (s) * 16384;                      \
        int bk = ((kt) & 7) * 32;                                                     \
        _Pragma("unroll")                                                             \
        for (int ii = 0; ii < 2; ii++) {                                              \
            int r = rL + ii * 64;                                                     \
            uint32_t doff = r * 64 + ((cL ^ ((r >> 1) & 3)) * 16);                    \
            cp_async16(ab + doff, Ag + (size_t)r * 512 + (kt) * 32 + cL * 8);         \
        }                                                                             \
        _Pragma("unroll")                                                             \
        for (int ii = 0; ii < 4; ii++) {                                              \
            int r = rL + ii * 64;                                                     \
            uint32_t doff = r * 64 + ((cL ^ ((r >> 1) & 3)) * 16);                    \
            cp_async16(bbx + doff, Bg + (size_t)r * 256 + bk + cL * 8);               \
        }                                                                             \
    } while (0)

    LOAD_STAGE(0, 0); CP_COMMIT();
    LOAD_STAGE(1, 1); CP_COMMIT();

    float acc[4][8][4];
#pragma unroll
    for (int i = 0; i < 4; i++)
#pragma unroll
        for (int j = 0; j < 8; j++)
#pragma unroll
            for (int qq = 0; qq < 4; qq++) acc[i][j][qq] = 0.f;

    const int aRow = lane & 15;
    const int aSel = lane >> 4;
    const int bRow = (lane & 7) + ((lane >> 4) << 3);
    const int bSel = (lane >> 3) & 1;

#pragma unroll 1
    for (int kt = 0; kt < 16; kt++) {
        CP_WAIT(1);
        __syncthreads();
        if (kt + 2 < 16) LOAD_STAGE((kt + 2) % GSTAGES, kt + 2);
        CP_COMMIT();

        const int st = kt % GSTAGES;
        const uint32_t ab = sAb + st * 8192;
        const uint32_t bb = sBb + st * 16384;

#pragma unroll
        for (int kf = 0; kf < 2; kf++) {
            uint32_t aF[4][4];
#pragma unroll
            for (int mf = 0; mf < 4; mf++) {
                int row = wr * 64 + mf * 16 + aRow;
                int ch  = (kf * 2 + aSel) ^ ((row >> 1) & 3);
                ldsm_x4(ab + row * 64 + ch * 16, aF[mf][0], aF[mf][1], aF[mf][2], aF[mf][3]);
            }
            uint32_t bF[4][4];
#pragma unroll
            for (int nf2 = 0; nf2 < 4; nf2++) {
                int row = wc * 64 + nf2 * 16 + bRow;
                int ch  = (kf * 2 + bSel) ^ ((row >> 1) & 3);
                ldsm_x4(bb + row * 64 + ch * 16, bF[nf2][0], bF[nf2][1], bF[nf2][2], bF[nf2][3]);
            }
#pragma unroll
            for (int mf = 0; mf < 4; mf++)
#pragma unroll
                for (int nf = 0; nf < 8; nf++) {
                    uint32_t b0 = bF[nf >> 1][(nf & 1) * 2 + 0];
                    uint32_t b1 = bF[nf >> 1][(nf & 1) * 2 + 1];
                    mma16816(acc[mf][nf], aF[mf], b0, b1);
                }
        }
    }

    const int rq = lane >> 2, cq = (lane & 3) * 2;
    const int rbase = row0 + wr * 64, cbase = col0 + wc * 64;
#pragma unroll
    for (int mf = 0; mf < 4; mf++) {
#pragma unroll
        for (int nf = 0; nf < 8; nf++) {
            int r  = rbase + mf * 16 + rq;
            int cc = cbase + nf * 8 + cq;
            float bz0 = bout[cc], bz1 = bout[cc + 1];
            float2 v0 = make_float2(acc[mf][nf][0] + bz0, acc[mf][nf][1] + bz1);
            float2 v1 = make_float2(acc[mf][nf][2] + bz0, acc[mf][nf][3] + bz1);
            *(float2*)&out[(size_t)r * VV + cc]       = v0;
            *(float2*)&out[(size_t)(r + 8) * VV + cc] = v1;
        }
    }
#undef LOAD_STAGE
}

// ---------------------------------------------------------------------------
extern "C" void kernel_launch(void* const* d_in, const int* in_sizes, int n_in,
                              void* d_out, int out_size) {
    const int*   inputs = (const int*)  d_in[0];
    const float* ann    = (const float*)d_in[1];
    const float* hinit  = (const float*)d_in[2];
    const float* emb    = (const float*)d_in[3];
    const float* W1     = (const float*)d_in[4];
    const float* b1     = (const float*)d_in[5];
    const float* W2     = (const float*)d_in[6];
    /* b2 (d_in[7]) cancels in softmax */
    const float* Wiz    = (const float*)d_in[8];
    const float* biz    = (const float*)d_in[9];
    const float* Wir    = (const float*)d_in[10];
    const float* bir    = (const float*)d_in[11];
    const float* Wih    = (const float*)d_in[12];
    const float* bih    = (const float*)d_in[13];
    const float* Whz    = (const float*)d_in[14];
    const float* bhz    = (const float*)d_in[15];
    const float* Whr    = (const float*)d_in[16];
    const float* bhr    = (const float*)d_in[17];
    const float* Whh    = (const float*)d_in[18];
    const float* bhh    = (const float*)d_in[19];
    const float* Wout   = (const float*)d_in[20];
    const float* bout   = (const float*)d_in[21];

    float* out = (float*)d_out;
    float* att = out + (size_t)BB * TT * VV;

    static int attr_set = 0;
    if (!attr_set) {
        cudaFuncSetAttribute(recurrence_kernel,
                             cudaFuncAttributeMaxDynamicSharedMemorySize, REC_DSMEM);
        attr_set = 1;
    }

    prep_kernel<<<256, 256>>>(W1, Wiz, Wir, Wih, Whz, bhz, Whr, bhr, Whh, bhh);
    combo_kernel<<<4896, 128>>>(ann, emb, inputs, Wout, b1, biz, bir, bih);
    recurrence_kernel<<<128, 512, REC_DSMEM>>>(hinit, W2, att);
    gemm_mma_kernel<<<dim3(16, 125), 256>>>(bout, out);
}

// round 14
// speedup vs baseline: 1.1843x; 1.1843x over previous
#include <cuda_runtime.h>
#include <cuda_fp16.h>
#include <cstdint>

// Problem constants
#define BB   32
#define TT   64
#define SS   64
#define HH   256
#define VV   32000

// ---------------------------------------------------------------------------
// PTX helpers
// ---------------------------------------------------------------------------
__device__ __forceinline__ uint32_t smem_u32(const void* p) {
    uint32_t a;
    asm("{ .reg .u64 t; cvta.to.shared.u64 t, %1; cvt.u32.u64 %0, t; }" : "=r"(a) : "l"(p));
    return a;
}
__device__ __forceinline__ void cp_async16(uint32_t dst, const void* src) {
    asm volatile("cp.async.cg.shared.global [%0], [%1], 16;" :: "r"(dst), "l"(src));
}
#define CP_COMMIT() asm volatile("cp.async.commit_group;" ::: "memory")
#define CP_WAIT(n)  asm volatile("cp.async.wait_group %0;" :: "n"(n) : "memory")

__device__ __forceinline__ void ldsm_x4(uint32_t addr, uint32_t& r0, uint32_t& r1,
                                        uint32_t& r2, uint32_t& r3) {
    asm volatile("ldmatrix.sync.aligned.m8n8.x4.shared.b16 {%0,%1,%2,%3}, [%4];"
                 : "=r"(r0), "=r"(r1), "=r"(r2), "=r"(r3) : "r"(addr));
}
__device__ __forceinline__ void mma16816(float* c, const uint32_t* a,
                                         uint32_t b0, uint32_t b1) {
    asm volatile("mma.sync.aligned.m16n8k16.row.col.f32.f16.f16.f32 "
                 "{%0,%1,%2,%3}, {%4,%5,%6,%7}, {%8,%9}, {%0,%1,%2,%3};"
                 : "+f"(c[0]), "+f"(c[1]), "+f"(c[2]), "+f"(c[3])
                 : "r"(a[0]), "r"(a[1]), "r"(a[2]), "r"(a[3]), "r"(b0), "r"(b1));
}
__device__ __forceinline__ uint32_t ctarank() {
    uint32_t r; asm("mov.u32 %0, %%cluster_ctarank;" : "=r"(r)); return r;
}
__device__ __forceinline__ uint32_t mapa_u32(uint32_t laddr, uint32_t rank) {
    uint32_t r;
    asm("mapa.shared::cluster.u32 %0, %1, %2;" : "=r"(r) : "r"(laddr), "r"(rank));
    return r;
}
__device__ __forceinline__ void st_cluster_f32(uint32_t addr, float v) {
    asm volatile("st.shared::cluster.f32 [%0], %1;" :: "r"(addr), "f"(v) : "memory");
}
#define CLUSTER_SYNC() do { \
    asm volatile("barrier.cluster.arrive.aligned;" ::: "memory"); \
    asm volatile("barrier.cluster.wait.aligned;" ::: "memory"); \
} while (0)
#define CLUSTER_ARRIVE() asm volatile("barrier.cluster.arrive.aligned;" ::: "memory")
#define CLUSTER_WAIT()   asm volatile("barrier.cluster.wait.aligned;" ::: "memory")

// ---------------------------------------------------------------------------
// Device scratch
// ---------------------------------------------------------------------------
__device__ __align__(16) float g_Wcat[256 * 1024];     // [k][qproj|Whz|Whr|Whh]
__device__ __align__(16) float g_bcat[1024];
__device__ __align__(16) float g_annprojB[2048 * 256]; // [(b*S+s)][256]  (+b1)
__device__ __align__(16) float g_annWi[2048 * 768];    // [(b*S+s)][768]
__device__ __align__(16) float g_xproj[2048 * 768];    // [(t*B+b)][768]  (+bi*)
__device__ __align__(16) __half g_Ah[2048 * 512];      // [A_hi(256)|A_lo(256)]
__device__ __align__(16) __half g_Bh[32000L * 256];    // Wout B_hi, K-major
__device__ __align__(16) __half g_Bch[1792 * 256];     // combo B (Wann|Wx), K-major fp16
__device__ __align__(16) __half g_A1h[2048 * 512];     // ann  hi|lo
__device__ __align__(16) __half g_A2h[2048 * 512];     // emb-gather hi|lo

// ---------------------------------------------------------------------------
// K0: build fused weights + fp16 operands for the combo HMMA
// ---------------------------------------------------------------------------
__global__ void prep_kernel(const float* __restrict__ W1,
                            const float* __restrict__ Wiz, const float* __restrict__ Wir,
                            const float* __restrict__ Wih,
                            const float* __restrict__ Whz, const float* __restrict__ bhz,
                            const float* __restrict__ Whr, const float* __restrict__ bhr,
                            const float* __restrict__ Whh, const float* __restrict__ bhh,
                            const float* __restrict__ ann, const float* __restrict__ emb,
                            const int* __restrict__ inputs) {
    int idx = blockIdx.x * blockDim.x + threadIdx.x;
    int stride = gridDim.x * blockDim.x;
    for (int i = idx; i < 256 * 1024; i += stride) {
        int k = i >> 10, j = i & 1023;
        float wc;
        if (j < 256)      wc = W1[k * 256 + j];
        else if (j < 512) wc = Whz[k * 256 + j - 256];
        else if (j < 768) wc = Whr[k * 256 + j - 512];
        else              wc = Whh[k * 256 + j - 768];
        g_Wcat[i] = wc;
    }
    // combo B: [j 0..1791][k 0..255] fp16
    for (int i = idx; i < 1792 * 256; i += stride) {
        int j = i >> 8, k = i & 255;
        float w;
        if (j < 256)       w = W1[(256 + k) * 256 + j];
        else if (j < 512)  w = Wiz[k * 256 + (j - 256)];
        else if (j < 768)  w = Wir[k * 256 + (j - 512)];
        else if (j < 1024) w = Wih[k * 256 + (j - 768)];
        else if (j < 1280) w = Wiz[(256 + k) * 256 + (j - 1024)];
        else if (j < 1536) w = Wir[(256 + k) * 256 + (j - 1280)];
        else               w = Wih[(256 + k) * 256 + (j - 1536)];
        g_Bch[i] = __float2half(w);
    }
    // A1: ann rows, hi|lo
    for (int i = idx; i < 2048 * 256; i += stride) {
        int r = i >> 8, k = i & 255;
        float v = ann[i];
        __half hi = __float2half(v);
        g_A1h[(size_t)r * 512 + k]       = hi;
        g_A1h[(size_t)r * 512 + 256 + k] = __float2half(v - __half2float(hi));
    }
    // A2: emb-gather rows (r -> t=r>>5, b=r&31), hi|lo
    for (int i = idx; i < 2048 * 256; i += stride) {
        int r = i >> 8, k = i & 255;
        int tok = inputs[(r & 31) * TT + (r >> 5)];
        float v = emb[(size_t)tok * 256 + k];
        __half hi = __float2half(v);
        g_A2h[(size_t)r * 512 + k]       = hi;
        g_A2h[(size_t)r * 512 + 256 + k] = __float2half(v - __half2float(hi));
    }
    for (int i = idx; i < 1024; i += stride) {
        float bv = 0.f;
        if (i >= 256 && i < 512)      bv = bhz[i - 256];
        else if (i >= 512 && i < 768) bv = bhr[i - 512];
        else if (i >= 768)            bv = bhh[i - 768];
        g_bcat[i] = bv;
    }
}

// ---------------------------------------------------------------------------
// K0b: Wout -> g_Bh fp16 (transpose via smem)
// ---------------------------------------------------------------------------
__global__ void __launch_bounds__(128)
bconv_kernel(const float* __restrict__ Wout) {
    __shared__ __align__(16) float sw[32 * 68];
    const int tid = threadIdx.x;
    int b3 = blockIdx.x;
    int k0 = (b3 & 7) * 32, n0 = (b3 >> 3) * 64;
    for (int i = tid; i < 32 * 64; i += 128) {
        int k = i >> 6, n = i & 63;
        sw[k * 68 + n] = Wout[(size_t)(k0 + k) * VV + n0 + n];
    }
    __syncthreads();
    const int n = tid >> 1, kh = (tid & 1) * 16;
    __align__(16) __half vals[16];
#pragma unroll
    for (int j = 0; j < 16; j++) vals[j] = __float2half(sw[(kh + j) * 68 + n]);
    __half* dst = g_Bh + (size_t)(n0 + n) * 256 + k0 + kh;
    *(uint4*)dst       = ((const uint4*)vals)[0];
    *(uint4*)(dst + 8) = ((const uint4*)vals)[1];
}

// ---------------------------------------------------------------------------
// K1: combo HMMA — D[2048,1792] = A(1|2)[2048,512] @ Bch^T, routing epilogue.
// R12-style: CTA 128x128, 4 warps of 64x64, 3-stage cp.async, B reuse kt&7.
// grid.y 0..7 -> m1 (A1, cols 0..1023); 8..13 -> m2 (A2, cols 1024..1791)
// ---------------------------------------------------------------------------
#define GSTAGES 3

__global__ void __launch_bounds__(128, 2)
combo_mma_kernel(const float* __restrict__ b1, const float* __restrict__ biz,
                 const float* __restrict__ bir, const float* __restrict__ bih) {
    __shared__ __align__(128) __half sA[GSTAGES][128 * 32];
    __shared__ __align__(128) __half sB[GSTAGES][128 * 32];

    const int tid  = threadIdx.x;
    const int lane = tid & 31, wid = tid >> 5;
    const int wr = wid >> 1, wc = wid & 1;
    const int row0 = blockIdx.x * 128;
    const bool m1 = blockIdx.y < 8;
    const int col0 = m1 ? blockIdx.y * 128 : (blockIdx.y - 8) * 128;
    const int bcol0 = m1 ? col0 : 1024 + col0;

    const __half* Ag = (m1 ? g_A1h : g_A2h) + (size_t)row0 * 512;
    const __half* Bg = g_Bch + (size_t)bcol0 * 256;

    const uint32_t sAb = smem_u32(sA);
    const uint32_t sBb = smem_u32(sB);

    const int cA0 = tid & 3;
    const int rL  = tid >> 2;

#define LOAD_STAGE(s, kt) do {                                                        \
        uint32_t ab = sAb + (s) * 8192, bbx = sBb + (s) * 8192;                       \
        int bk = ((kt) & 7) * 32;                                                     \
        _Pragma("unroll")                                                             \
        for (int ii = 0; ii < 4; ii++) {                                              \
            int r = rL + ii * 32;                                                     \
            uint32_t doff = r * 64 + ((cA0 ^ ((r >> 1) & 3)) * 16);                   \
            cp_async16(ab + doff,  Ag + (size_t)r * 512 + (kt) * 32 + cA0 * 8);       \
            cp_async16(bbx + doff, Bg + (size_t)r * 256 + bk + cA0 * 8);              \
        }                                                                             \
    } while (0)

    LOAD_STAGE(0, 0); CP_COMMIT();
    LOAD_STAGE(1, 1); CP_COMMIT();

    float acc[4][8][4];
#pragma unroll
    for (int i = 0; i < 4; i++)
#pragma unroll
        for (int j = 0; j < 8; j++)
#pragma unroll
            for (int qq = 0; qq < 4; qq++) acc[i][j][qq] = 0.f;

    const int aRow = lane & 15, aSel = lane >> 4;
    const int bRow = (lane & 7) + ((lane >> 4) << 3), bSel = (lane >> 3) & 1;

#pragma unroll 1
    for (int kt = 0; kt < 16; kt++) {
        CP_WAIT(1);
        __syncthreads();
        if (kt + 2 < 16) LOAD_STAGE((kt + 2) % GSTAGES, kt + 2);
        CP_COMMIT();

        const int st = kt % GSTAGES;
        const uint32_t ab = sAb + st * 8192;
        const uint32_t bb = sBb + st * 8192;

#pragma unroll
        for (int kf = 0; kf < 2; kf++) {
            uint32_t aF[4][4];
#pragma unroll
            for (int mf = 0; mf < 4; mf++) {
                int row = wr * 64 + mf * 16 + aRow;
                int ch  = (kf * 2 + aSel) ^ ((row >> 1) & 3);
                ldsm_x4(ab + row * 64 + ch * 16, aF[mf][0], aF[mf][1], aF[mf][2], aF[mf][3]);
            }
            uint32_t bF[4][4];
#pragma unroll
            for (int nf2 = 0; nf2 < 4; nf2++) {
                int row = wc * 64 + nf2 * 16 + bRow;
                int ch  = (kf * 2 + bSel) ^ ((row >> 1) & 3);
                ldsm_x4(bb + row * 64 + ch * 16, bF[nf2][0], bF[nf2][1], bF[nf2][2], bF[nf2][3]);
            }
#pragma unroll
            for (int mf = 0; mf < 4; mf++)
#pragma unroll
                for (int nf = 0; nf < 8; nf++)
                    mma16816(acc[mf][nf], aF[mf],
                             bF[nf >> 1][(nf & 1) * 2],
                             bF[nf >> 1][(nf & 1) * 2 + 1]);
        }
    }

    const int rq = lane >> 2, cq = (lane & 3) * 2;
    const int rbase = row0 + wr * 64;
#pragma unroll
    for (int mf = 0; mf < 4; mf++) {
#pragma unroll
        for (int nf = 0; nf < 8; nf++) {
            int cidx = col0 + wc * 64 + nf * 8 + cq;   // 0..1023 (m1) / 0..767 (m2)
#pragma unroll
            for (int hh = 0; hh < 2; hh++) {
                int r = rbase + mf * 16 + rq + hh * 8;
                float v0 = acc[mf][nf][hh * 2 + 0];
                float v1 = acc[mf][nf][hh * 2 + 1];
                if (m1) {
                    if (cidx < 256) {
                        g_annprojB[(size_t)r * 256 + cidx]     = v0 + b1[cidx];
                        g_annprojB[(size_t)r * 256 + cidx + 1] = v1 + b1[cidx + 1];
                    } else {
                        g_annWi[(size_t)r * 768 + cidx - 256]     = v0;
                        g_annWi[(size_t)r * 768 + cidx - 256 + 1] = v1;
                    }
                } else {
                    float bz0, bz1;
                    if (cidx < 256)      { bz0 = biz[cidx];       bz1 = biz[cidx + 1]; }
                    else if (cidx < 512) { bz0 = bir[cidx - 256]; bz1 = bir[cidx - 255]; }
                    else                 { bz0 = bih[cidx - 512]; bz1 = bih[cidx - 511]; }
                    g_xproj[(size_t)r * 768 + cidx]     = v0 + bz0;
                    g_xproj[(size_t)r * 768 + cidx + 1] = v1 + bz1;
                }
            }
        }
    }
#undef LOAD_STAGE
}

// ---------------------------------------------------------------------------
// K3: clustered recurrence (identical to R10/R12 - passing)
// ---------------------------------------------------------------------------
#define O_WS   0
#define O_QT   32768
#define O_TILE 36864
#define O_HS   49152
#define O_HC   49664
#define O_PA   49920
#define O_UPA  50944
#define O_AL   51968
#define O_ZR   52096
#define O_PHB  52224
#define O_BS   52288
#define O_W2   52416
#define REC_NF 52448
#define REC_DSMEM (REC_NF * 4)

__global__ void __launch_bounds__(512, 1) __cluster_dims__(8, 1, 1)
recurrence_kernel(const float* __restrict__ hidden_init,
                  const float* __restrict__ W2,
                  float* __restrict__ att_out) {
    extern __shared__ __align__(16) float dsm[];

    const int tid = threadIdx.x;
    const uint32_t q = ctarank();
    const int b0 = (blockIdx.x >> 3) * 2;
    const uint32_t sbase = smem_u32(dsm);

    for (int i = tid; i < 256 * 128; i += 512) {
        int k = i >> 7, j = i & 127;
        int gcol = (j >> 5) * 256 + (int)q * 32 + (j & 31);
        dsm[O_WS + k * 128 + j] = g_Wcat[k * 1024 + gcol];
    }
    for (int i = tid; i < 2 * 32 * 64; i += 512) {
        int bb = i >> 11, c = (i >> 6) & 31, s = i & 63;
        dsm[O_QT + i] = g_annprojB[(size_t)((b0 + bb) * 64 + s) * 256 + q * 32 + c];
    }
    for (int i = tid; i < 2 * 64 * 96; i += 512) {
        int bb = i / 6144, rem = i % 6144;
        int s = rem / 96, c = rem % 96;
        dsm[O_TILE + i] = g_annWi[(size_t)((b0 + bb) * 64 + s) * 768
                                  + (c >> 5) * 256 + q * 32 + (c & 31)];
    }
    if (tid < 128) {
        int gcol = (tid >> 5) * 256 + (int)q * 32 + (tid & 31);
        dsm[O_BS + tid] = g_bcat[gcol];
    }
    if (tid >= 128 && tid < 160) dsm[O_W2 + tid - 128] = W2[q * 32 + (tid - 128)];
    for (int i = tid; i < 512; i += 512)
        dsm[O_HS + i] = hidden_init[(b0 + (i >> 8)) * 256 + (i & 255)];
    __syncthreads();
    CLUSTER_SYNC();

    const int gbb = (tid >= 96 && tid < 192) ? 1 : 0;
    const int gcc = (tid < 192) ? (tid - gbb * 96) : 0;
    const size_t xoff = (size_t)((gcc >> 5) * 256 + (int)q * 32 + (gcc & 31));
    float xp = 0.f;
    if (tid < 192)
        xp = g_xproj[(size_t)(b0 + gbb) * 768 + xoff];

#pragma unroll 1
    for (int t = 0; t < TT; t++) {
        {
            const int j = tid & 127;
            const int kq = tid >> 7;
            const float* wp = &dsm[O_WS + kq * 64 * 128 + j];
            const float* h0 = &dsm[O_HS + kq * 64];
            const float* h1 = &dsm[O_HS + 256 + kq * 64];
            float a0 = 0.f, a1 = 0.f;
#pragma unroll
            for (int k = 0; k < 64; k += 4) {
                float4 hv0 = *(const float4*)(h0 + k);
                float4 hv1 = *(const float4*)(h1 + k);
                float w0 = wp[k * 128], w1 = wp[(k + 1) * 128];
                float w2v = wp[(k + 2) * 128], w3 = wp[(k + 3) * 128];
                a0 += hv0.x * w0 + hv0.y * w1 + hv0.z * w2v + hv0.w * w3;
                a1 += hv1.x * w0 + hv1.y * w1 + hv1.z * w2v + hv1.w * w3;
            }
            dsm[O_PA + kq * 256 + j]       = a0;
            dsm[O_PA + kq * 256 + 128 + j] = a1;
        }
        __syncthreads();
        if (tid < 256) {
            int bb = tid >> 7, jj = tid & 127;
            float v = dsm[O_BS + jj]
                    + dsm[O_PA + bb * 128 + jj]       + dsm[O_PA + 256 + bb * 128 + jj]
                    + dsm[O_PA + 512 + bb * 128 + jj] + dsm[O_PA + 768 + bb * 128 + jj];
            dsm[O_HC + bb * 128 + jj] = v;
        }
        __syncthreads();

        if (tid < 128) {
            const int bb = tid >> 6, s = tid & 63;
            const float* qt = &dsm[O_QT + bb * 2048 + s];
            const float* hq = &dsm[O_HC + bb * 128];
            const float* w2 = &dsm[O_W2];
            float u0 = 0.f, u1 = 0.f;
#pragma unroll
            for (int c = 0; c < 32; c += 4) {
                float4 hv = *(const float4*)(hq + c);
                float4 wv = *(const float4*)(w2 + c);
                u0 += wv.x * fmaxf(hv.x + qt[c * 64], 0.f)
                    + wv.y * fmaxf(hv.y + qt[(c + 1) * 64], 0.f);
                u1 += wv.z * fmaxf(hv.z + qt[(c + 2) * 64], 0.f)
                    + wv.w * fmaxf(hv.w + qt[(c + 3) * 64], 0.f);
            }
            float u = u0 + u1;
            uint32_t la = sbase + (O_UPA + (int)q * 128 + tid) * 4;
#pragma unroll
            for (int rk = 0; rk < 8; rk++)
                st_cluster_f32(mapa_u32(la, rk), u);
        }
        CLUSTER_SYNC();

        if (tid < 64) {
            const int bb = tid >> 5, lane = tid & 31;
            float u0 = 0.f, u1 = 0.f;
#pragma unroll
            for (int r = 0; r < 8; r++) {
                u0 += dsm[O_UPA + r * 128 + bb * 64 + lane];
                u1 += dsm[O_UPA + r * 128 + bb * 64 + 32 + lane];
            }
            float m = fmaxf(u0, u1);
#pragma unroll
            for (int o = 16; o; o >>= 1) m = fmaxf(m, __shfl_xor_sync(0xffffffffu, m, o));
            float e0 = __expf(u0 - m), e1 = __expf(u1 - m);
            float sum = e0 + e1;
#pragma unroll
            for (int o = 16; o; o >>= 1) sum += __shfl_xor_sync(0xffffffffu, sum, o);
            float inv = 1.f / sum;
            float a0 = e0 * inv, a1 = e1 * inv;
            dsm[O_AL + bb * 64 + lane]      = a0;
            dsm[O_AL + bb * 64 + 32 + lane] = a1;
            if (q == 0) {
                att_out[((b0 + bb) * SS + lane) * TT + t]      = a0;
                att_out[((b0 + bb) * SS + 32 + lane) * TT + t] = a1;
            }
        }
        __syncthreads();

        if (tid < 192) {
            const float* tp = &dsm[O_TILE + gbb * 6144 + gcc];
            const float* ap = &dsm[O_AL + gbb * 64];
            float acc0 = 0.f, acc1 = 0.f;
#pragma unroll 8
            for (int s = 0; s < 64; s += 2) {
                acc0 += ap[s] * tp[s * 96];
                acc1 += ap[s + 1] * tp[(s + 1) * 96];
            }
            float pre = acc0 + acc1 + xp;
            if (gcc < 64) {
                float v = 1.f / (1.f + __expf(-(pre + dsm[O_HC + gbb * 128 + 32 + gcc])));
                dsm[O_ZR + gbb * 64 + gcc] = v;
            } else {
                dsm[O_PHB + gbb * 32 + gcc - 64] = pre;
            }
        }
        __syncthreads();

        if (tid < 64) {
            int bb = tid >> 5, jj = tid & 31;
            int dg = (int)q * 32 + jj;
            float z = dsm[O_ZR + bb * 64 + jj];
            float r = dsm[O_ZR + bb * 64 + 32 + jj];
            float g = tanhf(dsm[O_PHB + bb * 32 + jj] + r * dsm[O_HC + bb * 128 + 96 + jj]);
            float hold = dsm[O_HS + bb * 256 + dg];
            float hn = (1.f - z) * g + z * hold;
            uint32_t la = sbase + (O_HS + bb * 256 + dg) * 4;
#pragma unroll
            for (int rk = 0; rk < 8; rk++)
                st_cluster_f32(mapa_u32(la, rk), hn);
            __half hi = __float2half(hn);
            __half lo = __float2half(hn - __half2float(hi));
            size_t rb = (size_t)((b0 + bb) * 64 + t) * 512;
            g_Ah[rb + dg]       = hi;
            g_Ah[rb + 256 + dg] = lo;
        }
        CLUSTER_ARRIVE();
        if (tid < 192 && t + 1 < TT)
            xp = g_xproj[(size_t)((t + 1) * 32 + b0 + gbb) * 768 + xoff];
        CLUSTER_WAIT();
    }
}

// ---------------------------------------------------------------------------
// K4: HMMA fp16 GEMM — exact R12 version (197us proven): CTA 128x128,
// 4 warps of 64x64, 128 threads, 2 CTAs/SM, 3-stage cp.async.
// ---------------------------------------------------------------------------
__global__ void __launch_bounds__(128, 2)
gemm_mma_kernel(const float* __restrict__ bout, float* __restrict__ out) {
    __shared__ __align__(128) __half sA[GSTAGES][128 * 32];
    __shared__ __align__(128) __half sB[GSTAGES][128 * 32];

    const int tid  = threadIdx.x;
    const int lane = tid & 31, wid = tid >> 5;
    const int wr = wid >> 1, wc = wid & 1;
    const int row0 = blockIdx.x * 128, col0 = blockIdx.y * 128;

    const __half* Ag = g_Ah + (size_t)row0 * 512;
    const __half* Bg = g_Bh + (size_t)col0 * 256;

    const uint32_t sAb = smem_u32(sA);
    const uint32_t sBb = smem_u32(sB);

    const int cA0 = tid & 3;
    const int rL  = tid >> 2;

#define LOAD_STAGE(s, kt) do {                                                        \
        uint32_t ab = sAb + (s) * 8192, bbx = sBb + (s) * 8192;                       \
        int bk = ((kt) & 7) * 32;                                                     \
        _Pragma("unroll")                                                             \
        for (int ii = 0; ii < 4; ii++) {                                              \
            int r = rL + ii * 32;                                                     \
            uint32_t doff = r * 64 + ((cA0 ^ ((r >> 1) & 3)) * 16);                   \
            cp_async16(ab + doff,  Ag + (size_t)r * 512 + (kt) * 32 + cA0 * 8);       \
            cp_async16(bbx + doff, Bg + (size_t)r * 256 + bk + cA0 * 8);              \
        }                                                                             \
    } while (0)

    LOAD_STAGE(0, 0); CP_COMMIT();
    LOAD_STAGE(1, 1); CP_COMMIT();

    float acc[4][8][4];
#pragma unroll
    for (int i = 0; i < 4; i++)
#pragma unroll
        for (int j = 0; j < 8; j++)
#pragma unroll
            for (int qq = 0; qq < 4; qq++) acc[i][j][qq] = 0.f;

    const int aRow = lane & 15, aSel = lane >> 4;
    const int bRow = (lane & 7) + ((lane >> 4) << 3), bSel = (lane >> 3) & 1;

#pragma unroll 1
    for (int kt = 0; kt < 16; kt++) {
        CP_WAIT(1);
        __syncthreads();
        if (kt + 2 < 16) LOAD_STAGE((kt + 2) % GSTAGES, kt + 2);
        CP_COMMIT();

        const int st = kt % GSTAGES;
        const uint32_t ab = sAb + st * 8192;
        const uint32_t bb = sBb + st * 8192;

#pragma unroll
        for (int kf = 0; kf < 2; kf++) {
            uint32_t aF[4][4];
#pragma unroll
            for (int mf = 0; mf < 4; mf++) {
                int row = wr * 64 + mf * 16 + aRow;
                int ch  = (kf * 2 + aSel) ^ ((row >> 1) & 3);
                ldsm_x4(ab + row * 64 + ch * 16, aF[mf][0], aF[mf][1], aF[mf][2], aF[mf][3]);
            }
            uint32_t bF[4][4];
#pragma unroll
            for (int nf2 = 0; nf2 < 4; nf2++) {
                int row = wc * 64 + nf2 * 16 + bRow;
                int ch  = (kf * 2 + bSel) ^ ((row >> 1) & 3);
                ldsm_x4(bb + row * 64 + ch * 16, bF[nf2][0], bF[nf2][1], bF[nf2][2], bF[nf2][3]);
            }
#pragma unroll
            for (int mf = 0; mf < 4; mf++)
#pragma unroll
                for (int nf = 0; nf < 8; nf++) {
                    uint32_t b0 = bF[nf >> 1][(nf & 1) * 2 + 0];
                    uint32_t b1 = bF[nf >> 1][(nf & 1) * 2 + 1];
                    mma16816(acc[mf][nf], aF[mf], b0, b1);
                }
        }
    }

    const int rq = lane >> 2, cq = (lane & 3) * 2;
    const int rbase = row0 + wr * 64, cbase = col0 + wc * 64;
#pragma unroll
    for (int mf = 0; mf < 4; mf++) {
#pragma unroll
        for (int nf = 0; nf < 8; nf++) {
            int r  = rbase + mf * 16 + rq;
            int cc = cbase + nf * 8 + cq;
            float bz0 = bout[cc], bz1 = bout[cc + 1];
            float2 v0 = make_float2(acc[mf][nf][0] + bz0, acc[mf][nf][1] + bz1);
            float2 v1 = make_float2(acc[mf][nf][2] + bz0, acc[mf][nf][3] + bz1);
            *(float2*)&out[(size_t)r * VV + cc]       = v0;
            *(float2*)&out[(size_t)(r + 8) * VV + cc] = v1;
        }
    }
#undef LOAD_STAGE
}

// ---------------------------------------------------------------------------
extern "C" void kernel_launch(void* const* d_in, const int* in_sizes, int n_in,
                              void* d_out, int out_size) {
    const int*   inputs = (const int*)  d_in[0];
    const float* ann    = (const float*)d_in[1];
    const float* hinit  = (const float*)d_in[2];
    const float* emb    = (const float*)d_in[3];
    const float* W1     = (const float*)d_in[4];
    const float* b1     = (const float*)d_in[5];
    const float* W2     = (const float*)d_in[6];
    /* b2 (d_in[7]) cancels in softmax */
    const float* Wiz    = (const float*)d_in[8];
    const float* biz    = (const float*)d_in[9];
    const float* Wir    = (const float*)d_in[10];
    const float* bir    = (const float*)d_in[11];
    const float* Wih    = (const float*)d_in[12];
    const float* bih    = (const float*)d_in[13];
    const float* Whz    = (const float*)d_in[14];
    const float* bhz    = (const float*)d_in[15];
    const float* Whr    = (const float*)d_in[16];
    const float* bhr    = (const float*)d_in[17];
    const float* Whh    = (const float*)d_in[18];
    const float* bhh    = (const float*)d_in[19];
    const float* Wout   = (const float*)d_in[20];
    const float* bout   = (const float*)d_in[21];

    float* out = (float*)d_out;
    float* att = out + (size_t)BB * TT * VV;

    static int attr_set = 0;
    if (!attr_set) {
        cudaFuncSetAttribute(recurrence_kernel,
                             cudaFuncAttributeMaxDynamicSharedMemorySize, REC_DSMEM);
        attr_set = 1;
    }

    prep_kernel<<<512, 256>>>(W1, Wiz, Wir, Wih, Whz, bhz, Whr, bhr, Whh, bhh,
                              ann, emb, inputs);
    bconv_kernel<<<4000, 128>>>(Wout);
    combo_mma_kernel<<<dim3(16, 14), 128>>>(b1, biz, bir, bih);
    recurrence_kernel<<<128, 512, REC_DSMEM>>>(hinit, W2, att);
    gemm_mma_kernel<<<dim3(16, 250), 128>>>(bout, out);
}